// round 2
// baseline (speedup 1.0000x reference)
#include <cuda_runtime.h>
#include <math.h>

// Problem constants
#define BB    2
#define NN    2048
#define CC    1024
#define HH    16
#define HD    64
#define NBH   (BB*HH)        // 32
#define MTOT  (BB*NN)        // 4096
#define X_ELEMS (BB*NN*CC)   // 4194304
#define ATT_SCALE 0.125f     // 64^-0.5

// Scratch (allocation-free: __device__ globals)
__device__ float g_qh[NBH*NN*HD];   // [bh][n][d]
__device__ float g_kh[NBH*NN*HD];
__device__ float g_vh[NBH*NN*HD];
__device__ float g_x [MTOT*CC];     // attention output, (b,n,C) layout
__device__ float g_rowmax[NBH*NN];
__device__ float g_rowinv[NBH*NN];

// ---------------------------------------------------------------------------
// 128x128 fp32 GEMM tile: out[m,n] = sum_k A[m,k]*W[n,k]   (both K-contiguous)
// 256 threads, 8x8 micro-tile per thread, BK=16.
// ---------------------------------------------------------------------------
__device__ __forceinline__ void gemm_tile_128(
    const float* __restrict__ A, const float* __restrict__ W,
    int m0, int n0, float acc[8][8],
    float (*As)[132], float (*Bs)[132])
{
    int tid = threadIdx.x;
    int tx = tid & 15, ty = tid >> 4;

    for (int kt = 0; kt < CC; kt += 16) {
        #pragma unroll
        for (int l = 0; l < 2; l++) {
            int vid = l * 256 + tid;
            int r   = vid >> 2;           // 0..127
            int kq  = (vid & 3) * 4;      // 0,4,8,12
            float4 av = *(const float4*)(A + (size_t)(m0 + r) * CC + kt + kq);
            As[kq+0][r] = av.x; As[kq+1][r] = av.y;
            As[kq+2][r] = av.z; As[kq+3][r] = av.w;
            float4 bv = *(const float4*)(W + (size_t)(n0 + r) * CC + kt + kq);
            Bs[kq+0][r] = bv.x; Bs[kq+1][r] = bv.y;
            Bs[kq+2][r] = bv.z; Bs[kq+3][r] = bv.w;
        }
        __syncthreads();
        #pragma unroll
        for (int k2 = 0; k2 < 16; k2++) {
            float a[8], b[8];
            *(float4*)(a)     = *(const float4*)&As[k2][ty*8];
            *(float4*)(a + 4) = *(const float4*)&As[k2][ty*8 + 4];
            *(float4*)(b)     = *(const float4*)&Bs[k2][tx*8];
            *(float4*)(b + 4) = *(const float4*)&Bs[k2][tx*8 + 4];
            #pragma unroll
            for (int i = 0; i < 8; i++)
                #pragma unroll
                for (int j = 0; j < 8; j++)
                    acc[i][j] += a[i] * b[j];
        }
        __syncthreads();
    }
}

// ---------------------------------------------------------------------------
// Kernel 1: QKV projection. grid (CC/128=8, MTOT/128=32, 3). z: 0=q,1=k,2=v.
// Writes head-transposed [bh][n][d] scratch.
// ---------------------------------------------------------------------------
__global__ void __launch_bounds__(256, 2) k_qkv(
    const float* __restrict__ q, const float* __restrict__ k,
    const float* __restrict__ v, const float* __restrict__ w)
{
    __shared__ float As[16][132];
    __shared__ float Bs[16][132];
    int z = blockIdx.z;
    const float* A = (z == 0) ? q : (z == 1) ? k : v;
    const float* W = w + (size_t)z * CC * CC;
    float* O = (z == 0) ? g_qh : (z == 1) ? g_kh : g_vh;

    float acc[8][8];
    #pragma unroll
    for (int i = 0; i < 8; i++)
        #pragma unroll
        for (int j = 0; j < 8; j++) acc[i][j] = 0.f;

    int m0 = blockIdx.y * 128, n0 = blockIdx.x * 128;
    gemm_tile_128(A, W, m0, n0, acc, As, Bs);

    int tx = threadIdx.x & 15, ty = threadIdx.x >> 4;
    int col = n0 + tx * 8;
    int h = col >> 6, d = col & 63;   // 8 cols never cross a head boundary
    #pragma unroll
    for (int i = 0; i < 8; i++) {
        int m = m0 + ty * 8 + i;
        int b = m >> 11, n = m & (NN - 1);
        float* dst = O + (((size_t)(b * HH + h) * NN + n) * HD + d);
        *(float4*)dst       = make_float4(acc[i][0], acc[i][1], acc[i][2], acc[i][3]);
        *(float4*)(dst + 4) = make_float4(acc[i][4], acc[i][5], acc[i][6], acc[i][7]);
    }
}

// ---------------------------------------------------------------------------
// Kernel 2: S = Q K^T * scale, causal mask, raw scores -> attn buffer.
// 128x128 tile per block, 8x8 micro, HD split into two 32-chunks.
// Online per-row max & sum-of-exp -> g_rowmax/g_rowinv.
// grid (1, NN/128=16, NBH=32), block 256 = (16,16).
// ---------------------------------------------------------------------------
__global__ void __launch_bounds__(256) k_scores(float* __restrict__ attn,
                                                const int* __restrict__ umask)
{
    int bh = blockIdx.z;
    int row0 = blockIdx.y * 128;
    int tid = threadIdx.x, tx = tid & 15, ty = tid >> 4;
    bool msk = (*umask) != 0;

    __shared__ float As[32][132];   // qT chunk: [kk][r]
    __shared__ float Bs[32][132];   // kT chunk: [kk][c]

    const float* qh = g_qh + (size_t)bh * NN * HD;
    const float* kh = g_kh + (size_t)bh * NN * HD;
    float* arow = attn + (size_t)bh * NN * NN;

    float mrun[8], srun[8];
    #pragma unroll
    for (int i = 0; i < 8; i++) { mrun[i] = -INFINITY; srun[i] = 0.f; }

    int ctmax = msk ? ((row0 + 127) >> 7) : (NN / 128 - 1);

    for (int ct = 0; ct <= ctmax; ct++) {
        float s[8][8];
        #pragma unroll
        for (int i = 0; i < 8; i++)
            #pragma unroll
            for (int j = 0; j < 8; j++) s[i][j] = 0.f;

        #pragma unroll
        for (int kc = 0; kc < HD; kc += 32) {
            __syncthreads();
            #pragma unroll
            for (int l = 0; l < 4; l++) {
                int vid = l * 256 + tid;
                int r = vid >> 3, kq = (vid & 7) * 4;  // r 0..127, kq 0..28
                float4 av = *(const float4*)(qh + (size_t)(row0 + r) * HD + kc + kq);
                As[kq+0][r] = av.x; As[kq+1][r] = av.y;
                As[kq+2][r] = av.z; As[kq+3][r] = av.w;
                float4 bv = *(const float4*)(kh + (size_t)(ct * 128 + r) * HD + kc + kq);
                Bs[kq+0][r] = bv.x; Bs[kq+1][r] = bv.y;
                Bs[kq+2][r] = bv.z; Bs[kq+3][r] = bv.w;
            }
            __syncthreads();
            #pragma unroll
            for (int k2 = 0; k2 < 32; k2++) {
                float a[8], b[8];
                *(float4*)(a)     = *(const float4*)&As[k2][ty*8];
                *(float4*)(a + 4) = *(const float4*)&As[k2][ty*8 + 4];
                *(float4*)(b)     = *(const float4*)&Bs[k2][tx*8];
                *(float4*)(b + 4) = *(const float4*)&Bs[k2][tx*8 + 4];
                #pragma unroll
                for (int i = 0; i < 8; i++)
                    #pragma unroll
                    for (int j = 0; j < 8; j++)
                        s[i][j] += a[i] * b[j];
            }
        }

        int cb = ct * 128 + tx * 8;
        #pragma unroll
        for (int i = 0; i < 8; i++) {
            int rg = row0 + ty * 8 + i;
            float sv[8];
            #pragma unroll
            for (int j = 0; j < 8; j++) {
                float val = s[i][j] * ATT_SCALE;
                if (msk && (cb + j) > rg) val = -INFINITY;
                sv[j] = val;
            }
            float* dst = arow + (size_t)rg * NN + cb;
            *(float4*)dst       = make_float4(sv[0], sv[1], sv[2], sv[3]);
            *(float4*)(dst + 4) = make_float4(sv[4], sv[5], sv[6], sv[7]);

            // online max / sum-of-exp across the 16 tx-lanes owning this row
            float tm = sv[0];
            #pragma unroll
            for (int j = 1; j < 8; j++) tm = fmaxf(tm, sv[j]);
            #pragma unroll
            for (int o = 8; o >= 1; o >>= 1)
                tm = fmaxf(tm, __shfl_xor_sync(0xffffffffu, tm, o, 16));
            float nm = fmaxf(mrun[i], tm);
            float ps = 0.f;
            #pragma unroll
            for (int j = 0; j < 8; j++) ps += __expf(sv[j] - nm);
            #pragma unroll
            for (int o = 8; o >= 1; o >>= 1)
                ps += __shfl_xor_sync(0xffffffffu, ps, o, 16);
            srun[i] = srun[i] * __expf(mrun[i] - nm) + ps;
            mrun[i] = nm;
        }
    }

    if (tx == 0) {
        #pragma unroll
        for (int i = 0; i < 8; i++) {
            int rg = row0 + ty * 8 + i;
            g_rowmax[bh * NN + rg] = mrun[i];
            g_rowinv[bh * NN + rg] = 1.0f / srun[i];
        }
    }
}

// ---------------------------------------------------------------------------
// Kernel 3: fused normalize + write attn probs + X = P·V.
// 128-row x 64-d tile per block, 8x4 micro, m-chunked at 32.
// Zero-fills masked upper triangle. grid (1, 16, 32), block 256.
// ---------------------------------------------------------------------------
__global__ void __launch_bounds__(256) k_av(float* __restrict__ attn,
                                            const int* __restrict__ umask)
{
    int bh = blockIdx.z;
    int row0 = blockIdx.y * 128;
    int tid = threadIdx.x, tx = tid & 15, ty = tid >> 4;
    bool msk = (*umask) != 0;

    __shared__ float Ps[32][132];  // P chunk transposed: [mm][r]
    __shared__ float Vs[32][68];   // V chunk: [mm][d]
    __shared__ float rm[128], ri[128];

    if (tid < 128) {
        rm[tid] = g_rowmax[bh * NN + row0 + tid];
        ri[tid] = g_rowinv[bh * NN + row0 + tid];
    }

    const float* vh = g_vh + (size_t)bh * NN * HD;
    float* arow = attn + (size_t)bh * NN * NN;

    float acc[8][4];
    #pragma unroll
    for (int i = 0; i < 8; i++)
        #pragma unroll
        for (int j = 0; j < 4; j++) acc[i][j] = 0.f;

    int mtmax = msk ? ((row0 + 127) >> 5) : (NN / 32 - 1);   // 32-wide m-chunks

    for (int mt = 0; mt <= mtmax; mt++) {
        __syncthreads();
        // load P chunk (128 rows x 32 cols): exp-normalize, write back, smem-transpose
        #pragma unroll
        for (int l = 0; l < 4; l++) {
            int vid = l * 256 + tid;
            int r = vid >> 3, mq = (vid & 7) * 4;
            int rg = row0 + r, cg = mt * 32 + mq;
            float4 svv = *(const float4*)(arow + (size_t)rg * NN + cg);
            float m = rm[r], is = ri[r];
            float4 p;
            p.x = (!msk || cg + 0 <= rg) ? __expf(svv.x - m) * is : 0.f;
            p.y = (!msk || cg + 1 <= rg) ? __expf(svv.y - m) * is : 0.f;
            p.z = (!msk || cg + 2 <= rg) ? __expf(svv.z - m) * is : 0.f;
            p.w = (!msk || cg + 3 <= rg) ? __expf(svv.w - m) * is : 0.f;
            *(float4*)(arow + (size_t)rg * NN + cg) = p;
            Ps[mq+0][r] = p.x; Ps[mq+1][r] = p.y;
            Ps[mq+2][r] = p.z; Ps[mq+3][r] = p.w;
        }
        // load V chunk (32 m-rows x 64 d)
        #pragma unroll
        for (int l = 0; l < 2; l++) {
            int vid = l * 256 + tid;
            int mm = vid >> 4, dq = (vid & 15) * 4;
            *(float4*)&Vs[mm][dq] = *(const float4*)(vh + (size_t)(mt * 32 + mm) * HD + dq);
        }
        __syncthreads();
        #pragma unroll
        for (int mm = 0; mm < 32; mm++) {
            float4 bv = *(const float4*)&Vs[mm][tx * 4];
            float a[8];
            *(float4*)(a)     = *(const float4*)&Ps[mm][ty*8];
            *(float4*)(a + 4) = *(const float4*)&Ps[mm][ty*8 + 4];
            #pragma unroll
            for (int i = 0; i < 8; i++) {
                acc[i][0] += a[i] * bv.x; acc[i][1] += a[i] * bv.y;
                acc[i][2] += a[i] * bv.z; acc[i][3] += a[i] * bv.w;
            }
        }
    }

    // zero-fill masked tiles strictly above the diagonal band
    if (msk) {
        float4 z = make_float4(0.f, 0.f, 0.f, 0.f);
        for (int mt = mtmax + 1; mt < NN / 32; mt++) {
            #pragma unroll
            for (int l = 0; l < 4; l++) {
                int vid = l * 256 + tid;
                int r = vid >> 3, mq = (vid & 7) * 4;
                *(float4*)(arow + (size_t)(row0 + r) * NN + mt * 32 + mq) = z;
            }
        }
    }

    int b = bh >> 4, h = bh & 15;
    #pragma unroll
    for (int i = 0; i < 8; i++) {
        int n = row0 + ty * 8 + i;
        float* dst = g_x + ((size_t)(b * NN + n) * CC + h * HD + tx * 4);
        *(float4*)dst = make_float4(acc[i][0], acc[i][1], acc[i][2], acc[i][3]);
    }
}

// ---------------------------------------------------------------------------
// Kernel 4: output projection  x = g_x @ proj_w^T + proj_b  -> d_out[0 : X_ELEMS)
// ---------------------------------------------------------------------------
__global__ void __launch_bounds__(256, 2) k_proj(
    const float* __restrict__ pw, const float* __restrict__ pb,
    float* __restrict__ xout)
{
    __shared__ float As[16][132];
    __shared__ float Bs[16][132];

    float acc[8][8];
    #pragma unroll
    for (int i = 0; i < 8; i++)
        #pragma unroll
        for (int j = 0; j < 8; j++) acc[i][j] = 0.f;

    int m0 = blockIdx.y * 128, n0 = blockIdx.x * 128;
    gemm_tile_128(g_x, pw, m0, n0, acc, As, Bs);

    int tx = threadIdx.x & 15, ty = threadIdx.x >> 4;
    float bias[8];
    *(float4*)(bias)     = *(const float4*)(pb + n0 + tx * 8);
    *(float4*)(bias + 4) = *(const float4*)(pb + n0 + tx * 8 + 4);

    #pragma unroll
    for (int i = 0; i < 8; i++) {
        int m = m0 + ty * 8 + i;
        float* dst = xout + (size_t)m * CC + n0 + tx * 8;
        *(float4*)dst = make_float4(acc[i][0] + bias[0], acc[i][1] + bias[1],
                                    acc[i][2] + bias[2], acc[i][3] + bias[3]);
        *(float4*)(dst + 4) = make_float4(acc[i][4] + bias[4], acc[i][5] + bias[5],
                                          acc[i][6] + bias[6], acc[i][7] + bias[7]);
    }
}

// ---------------------------------------------------------------------------
extern "C" void kernel_launch(void* const* d_in, const int* in_sizes, int n_in,
                              void* d_out, int out_size)
{
    const float* q      = (const float*)d_in[0];
    const float* k      = (const float*)d_in[1];
    const float* v      = (const float*)d_in[2];
    const float* qkv_w  = (const float*)d_in[3];
    const float* proj_w = (const float*)d_in[4];
    const float* proj_b = (const float*)d_in[5];
    const int*   umask  = (const int*)d_in[6];

    float* out  = (float*)d_out;
    float* xout = out;                 // x: (B,N,C) = 4,194,304 floats
    float* attn = out + X_ELEMS;       // attn: (B,H,N,N) = 134,217,728 floats

    dim3 g1(CC / 128, MTOT / 128, 3);
    k_qkv<<<g1, 256>>>(q, k, v, qkv_w);

    dim3 g2(1, NN / 128, NBH);
    k_scores<<<g2, 256>>>(attn, umask);
    k_av<<<g2, 256>>>(attn, umask);

    dim3 g4(CC / 128, MTOT / 128);
    k_proj<<<g4, 256>>>(proj_w, proj_b, xout);
}

// round 5
// speedup vs baseline: 1.1305x; 1.1305x over previous
#include <cuda_runtime.h>
#include <math.h>

// Problem constants
#define BB    2
#define NN    2048
#define CC    1024
#define HH    16
#define HD    64
#define NBH   (BB*HH)        // 32
#define MTOT  (BB*NN)        // 4096
#define X_ELEMS (BB*NN*CC)   // 4194304
#define ATT_SCALE 0.125f
#define NEGBIG   -1e30f

#define SA 20    // [rows][k16] pad stride (16+4): conflict-free frag loads
#define SV 72    // [k16][d64] pad stride (64+8)

// Scratch (allocation-free: __device__ globals)
__device__ float g_qh[NBH*NN*HD];
__device__ float g_kh[NBH*NN*HD];
__device__ float g_vh[NBH*NN*HD];
__device__ float g_x [MTOT*CC];
__device__ float g_rowmax[NBH*NN];
__device__ float g_rowinv[NBH*NN];

// ---------------------------------------------------------------------------
__device__ __forceinline__ unsigned f2tf(float x) {
    unsigned u; asm("cvt.rna.tf32.f32 %0, %1;" : "=r"(u) : "f"(x)); return u;
}

__device__ __forceinline__ void mma8(float* d,
    unsigned a0, unsigned a1, unsigned a2, unsigned a3,
    unsigned b0, unsigned b1)
{
    asm volatile(
        "mma.sync.aligned.m16n8k8.row.col.f32.tf32.tf32.f32 "
        "{%0,%1,%2,%3}, {%4,%5,%6,%7}, {%8,%9}, {%0,%1,%2,%3};"
        : "+f"(d[0]), "+f"(d[1]), "+f"(d[2]), "+f"(d[3])
        : "r"(a0), "r"(a1), "r"(a2), "r"(a3), "r"(b0), "r"(b1));
}

// split float4 into tf32 hi (rounded) + tf32 lo (residual), store to smem
__device__ __forceinline__ void split4(float4 v, float* hi, float* lo) {
    float h0 = __uint_as_float(f2tf(v.x));
    float h1 = __uint_as_float(f2tf(v.y));
    float h2 = __uint_as_float(f2tf(v.z));
    float h3 = __uint_as_float(f2tf(v.w));
    *(float4*)hi = make_float4(h0, h1, h2, h3);
    float l0 = __uint_as_float(f2tf(v.x - h0));
    float l1 = __uint_as_float(f2tf(v.y - h1));
    float l2 = __uint_as_float(f2tf(v.z - h2));
    float l3 = __uint_as_float(f2tf(v.w - h3));
    *(float4*)lo = make_float4(l0, l1, l2, l3);
}

// ---------------------------------------------------------------------------
// 3xTF32 MMA stage over one BK=16 chunk held in Ah/Al (A rows) and Bh/Bl (B rows).
// Warp tile 64x32: wm in {0,1} (64 rows), wn in {0..3} (32 cols). acc[4][4][4].
// ---------------------------------------------------------------------------
__device__ __forceinline__ void mma_chunk_128(
    const float* Ah, const float* Al, const float* Bh, const float* Bl,
    int wm, int wn, int g, int t, float acc[4][4][4])
{
    #pragma unroll
    for (int kk = 0; kk < 2; kk++) {
        int kb = kk * 8 + t;
        unsigned ah[4][4], al[4][4], bhf[4][2], blf[4][2];
        #pragma unroll
        for (int mi = 0; mi < 4; mi++) {
            int m = wm * 64 + mi * 16 + g;
            ah[mi][0] = __float_as_uint(Ah[m*SA + kb]);
            ah[mi][1] = __float_as_uint(Ah[(m+8)*SA + kb]);
            ah[mi][2] = __float_as_uint(Ah[m*SA + kb + 4]);
            ah[mi][3] = __float_as_uint(Ah[(m+8)*SA + kb + 4]);
            al[mi][0] = __float_as_uint(Al[m*SA + kb]);
            al[mi][1] = __float_as_uint(Al[(m+8)*SA + kb]);
            al[mi][2] = __float_as_uint(Al[m*SA + kb + 4]);
            al[mi][3] = __float_as_uint(Al[(m+8)*SA + kb + 4]);
        }
        #pragma unroll
        for (int nj = 0; nj < 4; nj++) {
            int n = wn * 32 + nj * 8 + g;
            bhf[nj][0] = __float_as_uint(Bh[n*SA + kb]);
            bhf[nj][1] = __float_as_uint(Bh[n*SA + kb + 4]);
            blf[nj][0] = __float_as_uint(Bl[n*SA + kb]);
            blf[nj][1] = __float_as_uint(Bl[n*SA + kb + 4]);
        }
        #pragma unroll
        for (int mi = 0; mi < 4; mi++)
            #pragma unroll
            for (int nj = 0; nj < 4; nj++) {
                mma8(acc[mi][nj], ah[mi][0],ah[mi][1],ah[mi][2],ah[mi][3], bhf[nj][0],bhf[nj][1]);
                mma8(acc[mi][nj], al[mi][0],al[mi][1],al[mi][2],al[mi][3], bhf[nj][0],bhf[nj][1]);
                mma8(acc[mi][nj], ah[mi][0],ah[mi][1],ah[mi][2],ah[mi][3], blf[nj][0],blf[nj][1]);
            }
    }
}

// ---------------------------------------------------------------------------
// Kernel 1: QKV projection. grid (8, 32, 3). z: 0=q,1=k,2=v. Head-transposed out.
// ---------------------------------------------------------------------------
__global__ void __launch_bounds__(256) k_qkv(
    const float* __restrict__ q, const float* __restrict__ k,
    const float* __restrict__ v, const float* __restrict__ w)
{
    __shared__ float Ah[128*SA], Al[128*SA], Bh[128*SA], Bl[128*SA];
    int z = blockIdx.z;
    const float* A = (z == 0) ? q : (z == 1) ? k : v;
    const float* W = w + (size_t)z * CC * CC;
    float* O = (z == 0) ? g_qh : (z == 1) ? g_kh : g_vh;

    int tid = threadIdx.x, lane = tid & 31, wid = tid >> 5;
    int wm = wid & 1, wn = wid >> 1, g = lane >> 2, t = lane & 3;
    int m0 = blockIdx.y * 128, n0 = blockIdx.x * 128;

    float acc[4][4][4];
    #pragma unroll
    for (int i = 0; i < 4; i++)
        #pragma unroll
        for (int j = 0; j < 4; j++)
            #pragma unroll
            for (int r = 0; r < 4; r++) acc[i][j][r] = 0.f;

    for (int kt = 0; kt < CC; kt += 16) {
        __syncthreads();
        #pragma unroll
        for (int l = 0; l < 2; l++) {
            int idx = l * 256 + tid;
            int r = idx >> 2, c = (idx & 3) << 2;
            float4 av = *(const float4*)(A + (size_t)(m0 + r) * CC + kt + c);
            split4(av, &Ah[r*SA + c], &Al[r*SA + c]);
            float4 bv = *(const float4*)(W + (size_t)(n0 + r) * CC + kt + c);
            split4(bv, &Bh[r*SA + c], &Bl[r*SA + c]);
        }
        __syncthreads();
        mma_chunk_128(Ah, Al, Bh, Bl, wm, wn, g, t, acc);
    }

    #pragma unroll
    for (int mi = 0; mi < 4; mi++)
        #pragma unroll
        for (int half = 0; half < 2; half++) {
            int m = m0 + wm * 64 + mi * 16 + g + half * 8;
            int b = m >> 11, n = m & (NN - 1);
            #pragma unroll
            for (int nj = 0; nj < 4; nj++) {
                int col = n0 + wn * 32 + nj * 8 + 2 * t;
                int h = col >> 6, d = col & 63;
                *(float2*)(O + (((size_t)(b * HH + h) * NN + n) * HD + d)) =
                    make_float2(acc[mi][nj][half*2], acc[mi][nj][half*2+1]);
            }
        }
}

// ---------------------------------------------------------------------------
// Kernel 2: scores S = qh·kh^T * scale (causal) -> attn; online row stats.
// grid (1, 16, 32), block 256. Heavy row-tiles scheduled first.
// ---------------------------------------------------------------------------
__global__ void __launch_bounds__(256) k_scores(float* __restrict__ attn,
                                                const int* __restrict__ umask)
{
    __shared__ float Ah[128*SA], Al[128*SA], Bh[128*SA], Bl[128*SA];
    __shared__ float redm[4][128], reds[4][128];

    int bh = blockIdx.z;
    int row0 = (int)(gridDim.y - 1 - blockIdx.y) * 128;
    int tid = threadIdx.x, lane = tid & 31, wid = tid >> 5;
    int wm = wid & 1, wn = wid >> 1, g = lane >> 2, t = lane & 3;
    bool msk = (*umask) != 0;

    const float* qh = g_qh + (size_t)bh * NN * HD;
    const float* kh = g_kh + (size_t)bh * NN * HD;
    float* arow = attn + (size_t)bh * NN * NN;

    float mrun[4][2], srun[4][2];
    #pragma unroll
    for (int i = 0; i < 4; i++) { mrun[i][0] = NEGBIG; mrun[i][1] = NEGBIG;
                                  srun[i][0] = 0.f;   srun[i][1] = 0.f; }

    int ctmax = msk ? (row0 >> 7) : (NN / 128 - 1);

    for (int ct = 0; ct <= ctmax; ct++) {
        float acc[4][4][4];
        #pragma unroll
        for (int i = 0; i < 4; i++)
            #pragma unroll
            for (int j = 0; j < 4; j++)
                #pragma unroll
                for (int r = 0; r < 4; r++) acc[i][j][r] = 0.f;

        #pragma unroll
        for (int kt = 0; kt < HD; kt += 16) {
            __syncthreads();
            #pragma unroll
            for (int l = 0; l < 2; l++) {
                int idx = l * 256 + tid;
                int r = idx >> 2, c = (idx & 3) << 2;
                float4 av = *(const float4*)(qh + (size_t)(row0 + r) * HD + kt + c);
                split4(av, &Ah[r*SA + c], &Al[r*SA + c]);
                float4 bv = *(const float4*)(kh + (size_t)(ct * 128 + r) * HD + kt + c);
                split4(bv, &Bh[r*SA + c], &Bl[r*SA + c]);
            }
            __syncthreads();
            mma_chunk_128(Ah, Al, Bh, Bl, wm, wn, g, t, acc);
        }

        int cbase = ct * 128 + wn * 32;
        #pragma unroll
        for (int mi = 0; mi < 4; mi++)
            #pragma unroll
            for (int half = 0; half < 2; half++) {
                int rg = row0 + wm * 64 + mi * 16 + g + half * 8;
                float vb[8];
                #pragma unroll
                for (int nj = 0; nj < 4; nj++) {
                    int cg = cbase + nj * 8 + 2 * t;
                    float ve = acc[mi][nj][half*2]   * ATT_SCALE;
                    float vo = acc[mi][nj][half*2+1] * ATT_SCALE;
                    if (msk && cg     > rg) ve = NEGBIG;
                    if (msk && cg + 1 > rg) vo = NEGBIG;
                    *(float2*)(arow + (size_t)rg * NN + cg) = make_float2(ve, vo);
                    vb[nj*2] = ve; vb[nj*2+1] = vo;
                }
                float tmax = vb[0];
                #pragma unroll
                for (int j = 1; j < 8; j++) tmax = fmaxf(tmax, vb[j]);
                float nm = fmaxf(mrun[mi][half], tmax);
                float ps = 0.f;
                if (nm > -1e29f) {
                    #pragma unroll
                    for (int j = 0; j < 8; j++) ps += __expf(vb[j] - nm);
                }
                srun[mi][half] = srun[mi][half] * __expf(mrun[mi][half] - nm) + ps;
                mrun[mi][half] = nm;
            }
    }

    // merge across the 4 lanes (t) sharing each row, then across the 4 wn warps
    #pragma unroll
    for (int mi = 0; mi < 4; mi++)
        #pragma unroll
        for (int half = 0; half < 2; half++) {
            float m1 = mrun[mi][half], s1 = srun[mi][half];
            #pragma unroll
            for (int o = 1; o <= 2; o <<= 1) {
                float m2 = __shfl_xor_sync(0xffffffffu, m1, o, 4);
                float s2 = __shfl_xor_sync(0xffffffffu, s1, o, 4);
                float nm = fmaxf(m1, m2);
                s1 = s1 * __expf(m1 - nm) + s2 * __expf(m2 - nm);
                m1 = nm;
            }
            if (t == 0) {
                int rl = wm * 64 + mi * 16 + g + half * 8;
                redm[wn][rl] = m1; reds[wn][rl] = s1;
            }
        }
    __syncthreads();
    if (tid < 128) {
        float m = fmaxf(fmaxf(redm[0][tid], redm[1][tid]),
                        fmaxf(redm[2][tid], redm[3][tid]));
        float s = reds[0][tid] * __expf(redm[0][tid] - m)
                + reds[1][tid] * __expf(redm[1][tid] - m)
                + reds[2][tid] * __expf(redm[2][tid] - m)
                + reds[3][tid] * __expf(redm[3][tid] - m);
        g_rowmax[bh * NN + row0 + tid] = m;
        g_rowinv[bh * NN + row0 + tid] = 1.0f / s;
    }
}

// ---------------------------------------------------------------------------
// Kernel 3: fused normalize + prob writeback + X = P·V (3xTF32 MMA).
// Block: 128 rows x 64 d-cols; warps 4m x 2n; per-warp 32x32 (2x4 mma tiles).
// grid (1, 16, 32). Heavy tiles first; zero-fills masked upper triangle.
// ---------------------------------------------------------------------------
__global__ void __launch_bounds__(256) k_av(float* __restrict__ attn,
                                            const int* __restrict__ umask)
{
    __shared__ float Ph[128*SA], Pl[128*SA], Vh[16*SV], Vl[16*SV];
    __shared__ float rm[128], ri[128];

    int bh = blockIdx.z;
    int row0 = (int)(gridDim.y - 1 - blockIdx.y) * 128;
    int tid = threadIdx.x, lane = tid & 31, wid = tid >> 5;
    int wm = wid & 3, wn = wid >> 2, g = lane >> 2, t = lane & 3;
    bool msk = (*umask) != 0;

    if (tid < 128) {
        rm[tid] = g_rowmax[bh * NN + row0 + tid];
        ri[tid] = g_rowinv[bh * NN + row0 + tid];
    }

    const float* vh = g_vh + (size_t)bh * NN * HD;
    float* arow = attn + (size_t)bh * NN * NN;

    float acc[2][4][4];
    #pragma unroll
    for (int i = 0; i < 2; i++)
        #pragma unroll
        for (int j = 0; j < 4; j++)
            #pragma unroll
            for (int r = 0; r < 4; r++) acc[i][j][r] = 0.f;

    int mtmax = msk ? ((row0 + 127) >> 4) : (NN / 16 - 1);

    for (int mt = 0; mt <= mtmax; mt++) {
        __syncthreads();
        // P chunk 128x16: load scores, exp-normalize, write probs back, split
        #pragma unroll
        for (int l = 0; l < 2; l++) {
            int idx = l * 256 + tid;
            int r = idx >> 2, c = (idx & 3) << 2;
            int rg = row0 + r, cg = mt * 16 + c;
            float4 s = *(const float4*)(arow + (size_t)rg * NN + cg);
            float m = rm[r], inv = ri[r];
            float4 p;
            p.x = (!msk || cg + 0 <= rg) ? __expf(s.x - m) * inv : 0.f;
            p.y = (!msk || cg + 1 <= rg) ? __expf(s.y - m) * inv : 0.f;
            p.z = (!msk || cg + 2 <= rg) ? __expf(s.z - m) * inv : 0.f;
            p.w = (!msk || cg + 3 <= rg) ? __expf(s.w - m) * inv : 0.f;
            *(float4*)(arow + (size_t)rg * NN + cg) = p;
            split4(p, &Ph[r*SA + c], &Pl[r*SA + c]);
        }
        // V chunk 16x64
        {
            int kv = tid >> 4, dv = (tid & 15) << 2;
            float4 vv = *(const float4*)(vh + (size_t)(mt * 16 + kv) * HD + dv);
            split4(vv, &Vh[kv*SV + dv], &Vl[kv*SV + dv]);
        }
        __syncthreads();

        #pragma unroll
        for (int kk = 0; kk < 2; kk++) {
            int kb = kk * 8 + t;
            unsigned ah[2][4], al[2][4], bhf[4][2], blf[4][2];
            #pragma unroll
            for (int mi = 0; mi < 2; mi++) {
                int m = wm * 32 + mi * 16 + g;
                ah[mi][0] = __float_as_uint(Ph[m*SA + kb]);
                ah[mi][1] = __float_as_uint(Ph[(m+8)*SA + kb]);
                ah[mi][2] = __float_as_uint(Ph[m*SA + kb + 4]);
                ah[mi][3] = __float_as_uint(Ph[(m+8)*SA + kb + 4]);
                al[mi][0] = __float_as_uint(Pl[m*SA + kb]);
                al[mi][1] = __float_as_uint(Pl[(m+8)*SA + kb]);
                al[mi][2] = __float_as_uint(Pl[m*SA + kb + 4]);
                al[mi][3] = __float_as_uint(Pl[(m+8)*SA + kb + 4]);
            }
            #pragma unroll
            for (int nj = 0; nj < 4; nj++) {
                int n = wn * 32 + nj * 8 + g;
                bhf[nj][0] = __float_as_uint(Vh[kb*SV + n]);
                bhf[nj][1] = __float_as_uint(Vh[(kb+4)*SV + n]);
                blf[nj][0] = __float_as_uint(Vl[kb*SV + n]);
                blf[nj][1] = __float_as_uint(Vl[(kb+4)*SV + n]);
            }
            #pragma unroll
            for (int mi = 0; mi < 2; mi++)
                #pragma unroll
                for (int nj = 0; nj < 4; nj++) {
                    mma8(acc[mi][nj], ah[mi][0],ah[mi][1],ah[mi][2],ah[mi][3], bhf[nj][0],bhf[nj][1]);
                    mma8(acc[mi][nj], al[mi][0],al[mi][1],al[mi][2],al[mi][3], bhf[nj][0],bhf[nj][1]);
                    mma8(acc[mi][nj], ah[mi][0],ah[mi][1],ah[mi][2],ah[mi][3], blf[nj][0],blf[nj][1]);
                }
        }
    }

    // zero-fill masked upper-triangle columns
    if (msk) {
        float4 z = make_float4(0.f, 0.f, 0.f, 0.f);
        for (int mt = mtmax + 1; mt < NN / 16; mt++) {
            #pragma unroll
            for (int l = 0; l < 2; l++) {
                int idx = l * 256 + tid;
                int r = idx >> 2, c = (idx & 3) << 2;
                *(float4*)(arow + (size_t)(row0 + r) * NN + mt * 16 + c) = z;
            }
        }
    }

    int b = bh >> 4, h = bh & 15;
    #pragma unroll
    for (int mi = 0; mi < 2; mi++)
        #pragma unroll
        for (int half = 0; half < 2; half++) {
            int n = row0 + wm * 32 + mi * 16 + g + half * 8;
            #pragma unroll
            for (int nj = 0; nj < 4; nj++) {
                int d = wn * 32 + nj * 8 + 2 * t;
                *(float2*)(g_x + ((size_t)(b * NN + n) * CC + h * HD + d)) =
                    make_float2(acc[mi][nj][half*2], acc[mi][nj][half*2+1]);
            }
        }
}

// ---------------------------------------------------------------------------
// Kernel 4: output projection x = g_x @ proj_w^T + proj_b
// ---------------------------------------------------------------------------
__global__ void __launch_bounds__(256) k_proj(
    const float* __restrict__ pw, const float* __restrict__ pb,
    float* __restrict__ xout)
{
    __shared__ float Ah[128*SA], Al[128*SA], Bh[128*SA], Bl[128*SA];
    int tid = threadIdx.x, lane = tid & 31, wid = tid >> 5;
    int wm = wid & 1, wn = wid >> 1, g = lane >> 2, t = lane & 3;
    int m0 = blockIdx.y * 128, n0 = blockIdx.x * 128;

    float acc[4][4][4];
    #pragma unroll
    for (int i = 0; i < 4; i++)
        #pragma unroll
        for (int j = 0; j < 4; j++)
            #pragma unroll
            for (int r = 0; r < 4; r++) acc[i][j][r] = 0.f;

    for (int kt = 0; kt < CC; kt += 16) {
        __syncthreads();
        #pragma unroll
        for (int l = 0; l < 2; l++) {
            int idx = l * 256 + tid;
            int r = idx >> 2, c = (idx & 3) << 2;
            float4 av = *(const float4*)(g_x + (size_t)(m0 + r) * CC + kt + c);
            split4(av, &Ah[r*SA + c], &Al[r*SA + c]);
            float4 bv = *(const float4*)(pw + (size_t)(n0 + r) * CC + kt + c);
            split4(bv, &Bh[r*SA + c], &Bl[r*SA + c]);
        }
        __syncthreads();
        mma_chunk_128(Ah, Al, Bh, Bl, wm, wn, g, t, acc);
    }

    #pragma unroll
    for (int mi = 0; mi < 4; mi++)
        #pragma unroll
        for (int half = 0; half < 2; half++) {
            int m = m0 + wm * 64 + mi * 16 + g + half * 8;
            #pragma unroll
            for (int nj = 0; nj < 4; nj++) {
                int col = n0 + wn * 32 + nj * 8 + 2 * t;
                float b0 = pb[col], b1 = pb[col + 1];
                *(float2*)(xout + (size_t)m * CC + col) =
                    make_float2(acc[mi][nj][half*2] + b0, acc[mi][nj][half*2+1] + b1);
            }
        }
}

// ---------------------------------------------------------------------------
extern "C" void kernel_launch(void* const* d_in, const int* in_sizes, int n_in,
                              void* d_out, int out_size)
{
    const float* q      = (const float*)d_in[0];
    const float* k      = (const float*)d_in[1];
    const float* v      = (const float*)d_in[2];
    const float* qkv_w  = (const float*)d_in[3];
    const float* proj_w = (const float*)d_in[4];
    const float* proj_b = (const float*)d_in[5];
    const int*   umask  = (const int*)d_in[6];

    float* out  = (float*)d_out;
    float* xout = out;                 // x: (B,N,C)
    float* attn = out + X_ELEMS;       // attn: (B,H,N,N)

    dim3 g1(CC / 128, MTOT / 128, 3);
    k_qkv<<<g1, 256>>>(q, k, v, qkv_w);

    dim3 g2(1, NN / 128, NBH);
    k_scores<<<g2, 256>>>(attn, umask);
    k_av<<<g2, 256>>>(attn, umask);

    dim3 g4(CC / 128, MTOT / 128);
    k_proj<<<g4, 256>>>(proj_w, proj_b, xout);
}